// round 1
// baseline (speedup 1.0000x reference)
#include <cuda_runtime.h>

#define NN   100000
#define NE   1600000
#define FIN  165
#define NEG  0.2f

// ---------------- scratch (static device globals; no runtime alloc) ----------------
__device__ __align__(16) float g_h1[(long)NN * 64];   // h1 = x@W1, [N,8,8]
__device__ float g_as1[NN * 8];
__device__ float g_ad1[NN * 8];
__device__ __align__(16) float g_S1[(long)NN * 64];   // unnormalized aggregation, layer1
__device__ float g_z1[NN * 8];                        // softmax denominators, layer1
__device__ __align__(8)  float g_h2[NN * 2];
__device__ float g_as2[NN];
__device__ float g_ad2[NN];
__device__ __align__(8)  float g_S2[NN * 2];
__device__ float g_z2[NN];
__device__ int   g_is64;

// ---------------- helpers ----------------
__device__ __forceinline__ float lrelu(float t) { return t > 0.f ? t : NEG * t; }

__device__ __forceinline__ void red_add_v4(float* p, float a, float b, float c, float d) {
    unsigned long long gp = (unsigned long long)__cvta_generic_to_global(p);
    asm volatile("red.global.add.v4.f32 [%0], {%1,%2,%3,%4};"
                 :: "l"(gp), "f"(a), "f"(b), "f"(c), "f"(d) : "memory");
}
__device__ __forceinline__ void red_add_v2(float* p, float a, float b) {
    unsigned long long gp = (unsigned long long)__cvta_generic_to_global(p);
    asm volatile("red.global.add.v2.f32 [%0], {%1,%2};"
                 :: "l"(gp), "f"(a), "f"(b) : "memory");
}

// ---------------- 0: edge_index dtype detection (int64 vs int32) ----------------
__global__ void detect_kernel(const long long* __restrict__ e) {
    long long v = e[threadIdx.x];
    int bad = (v < 0 || v >= NN);
    int any = __syncthreads_or(bad);
    if (threadIdx.x == 0) g_is64 = !any;
}

// ---------------- 1: h1 = x@W1, alphas, self-loop init of S1/z1 ----------------
// grid 3125 x 256; 32 nodes/block, thread (nl,h) computes h1[n][h][0..7]
#define GEMM1_SMEM ((FIN * 64 + 32 * FIN) * 4)
__global__ void __launch_bounds__(256)
gemm1_kernel(const float* __restrict__ x, const float* __restrict__ W1,
             const float* __restrict__ a1s, const float* __restrict__ a1d) {
    extern __shared__ float sm[];
    float* Ws = sm;              // [165][64]
    float* xs = sm + FIN * 64;   // [32][165]
    int tid = threadIdx.x;
    long base = (long)blockIdx.x * 32 * FIN;
    for (int i = tid; i < FIN * 64; i += 256) Ws[i] = W1[i];
    for (int i = tid; i < 32 * FIN; i += 256) xs[i] = x[base + i];
    __syncthreads();

    int nl = tid >> 3, h = tid & 7;
    const float* xr = xs + nl * FIN;
    const float* wp = Ws + h * 8;
    float acc[8] = {0.f, 0.f, 0.f, 0.f, 0.f, 0.f, 0.f, 0.f};
#pragma unroll 5
    for (int k = 0; k < FIN; ++k) {
        float xv = xr[k];
        float4 w0 = *reinterpret_cast<const float4*>(wp + (long)k * 64);
        float4 w1 = *reinterpret_cast<const float4*>(wp + (long)k * 64 + 4);
        acc[0] += xv * w0.x; acc[1] += xv * w0.y; acc[2] += xv * w0.z; acc[3] += xv * w0.w;
        acc[4] += xv * w1.x; acc[5] += xv * w1.y; acc[6] += xv * w1.z; acc[7] += xv * w1.w;
    }

    int n = blockIdx.x * 32 + nl;
    float as = 0.f, ad = 0.f;
#pragma unroll
    for (int j = 0; j < 8; ++j) {
        as += acc[j] * __ldg(&a1s[h * 8 + j]);
        ad += acc[j] * __ldg(&a1d[h * 8 + j]);
    }
    g_as1[n * 8 + h] = as;
    g_ad1[n * 8 + h] = ad;

    long o = (long)n * 64 + h * 8;
    *reinterpret_cast<float4*>(&g_h1[o])     = make_float4(acc[0], acc[1], acc[2], acc[3]);
    *reinterpret_cast<float4*>(&g_h1[o + 4]) = make_float4(acc[4], acc[5], acc[6], acc[7]);

    // self-loop contribution initializes S1/z1 (no memset needed)
    float w = __expf(lrelu(as + ad));
    g_z1[n * 8 + h] = w;
    *reinterpret_cast<float4*>(&g_S1[o])     = make_float4(w * acc[0], w * acc[1], w * acc[2], w * acc[3]);
    *reinterpret_cast<float4*>(&g_S1[o + 4]) = make_float4(w * acc[4], w * acc[5], w * acc[6], w * acc[7]);
}

// ---------------- 2: layer-1 edge scatter (8 threads/edge, one per head) ----------------
__global__ void __launch_bounds__(256)
edge1_kernel(const long long* __restrict__ eidx) {
    int idx = blockIdx.x * 256 + threadIdx.x;
    int e = idx >> 3;
    if (e >= NE) return;
    int h = idx & 7;
    int src, dst;
    if (g_is64) { src = (int)eidx[e]; dst = (int)eidx[NE + e]; }
    else { const int* e32 = (const int*)eidx; src = e32[e]; dst = e32[NE + e]; }

    float t = g_as1[src * 8 + h] + g_ad1[dst * 8 + h];
    float w = __expf(lrelu(t));
    atomicAdd(&g_z1[dst * 8 + h], w);

    long so = (long)src * 64 + h * 8;
    float4 x0 = *reinterpret_cast<const float4*>(&g_h1[so]);
    float4 x1 = *reinterpret_cast<const float4*>(&g_h1[so + 4]);
    float* s = &g_S1[(long)dst * 64 + h * 8];
    red_add_v4(s,     w * x0.x, w * x0.y, w * x0.z, w * x0.w);
    red_add_v4(s + 4, w * x1.x, w * x1.y, w * x1.z, w * x1.w);
}

// ---------------- 3: normalize+bias+elu, h2 = out1@W2, alphas2, self-loop init S2/z2 ----------------
// warp per node; lane handles cols (lane, lane+32)
__global__ void __launch_bounds__(256)
epi1_kernel(const float* __restrict__ b1, const float* __restrict__ W2,
            const float* __restrict__ a2s, const float* __restrict__ a2d) {
    int n = blockIdx.x * 8 + (threadIdx.x >> 5);
    int lane = threadIdx.x & 31;
    int c0 = lane, c1 = lane + 32;

    float v0 = g_S1[(long)n * 64 + c0] / g_z1[n * 8 + (c0 >> 3)] + __ldg(&b1[c0]);
    float v1 = g_S1[(long)n * 64 + c1] / g_z1[n * 8 + (c1 >> 3)] + __ldg(&b1[c1]);
    v0 = v0 > 0.f ? v0 : expm1f(v0);   // elu
    v1 = v1 > 0.f ? v1 : expm1f(v1);

    float p0 = v0 * __ldg(&W2[c0 * 2])     + v1 * __ldg(&W2[c1 * 2]);
    float p1 = v0 * __ldg(&W2[c0 * 2 + 1]) + v1 * __ldg(&W2[c1 * 2 + 1]);
#pragma unroll
    for (int o = 16; o; o >>= 1) {
        p0 += __shfl_xor_sync(0xffffffffu, p0, o);
        p1 += __shfl_xor_sync(0xffffffffu, p1, o);
    }
    if (lane == 0) {
        float as = p0 * __ldg(&a2s[0]) + p1 * __ldg(&a2s[1]);
        float ad = p0 * __ldg(&a2d[0]) + p1 * __ldg(&a2d[1]);
        float w = __expf(lrelu(as + ad));   // layer-2 self-loop
        g_h2[2 * n] = p0; g_h2[2 * n + 1] = p1;
        g_as2[n] = as;    g_ad2[n] = ad;
        g_z2[n] = w;
        g_S2[2 * n] = w * p0; g_S2[2 * n + 1] = w * p1;
    }
}

// ---------------- 4: layer-2 edge scatter (thread per edge) ----------------
__global__ void __launch_bounds__(256)
edge2_kernel(const long long* __restrict__ eidx) {
    int e = blockIdx.x * 256 + threadIdx.x;
    if (e >= NE) return;
    int src, dst;
    if (g_is64) { src = (int)eidx[e]; dst = (int)eidx[NE + e]; }
    else { const int* e32 = (const int*)eidx; src = e32[e]; dst = e32[NE + e]; }

    float t = g_as2[src] + g_ad2[dst];
    float w = __expf(lrelu(t));
    atomicAdd(&g_z2[dst], w);
    float2 hv = *reinterpret_cast<const float2*>(&g_h2[2 * src]);
    red_add_v2(&g_S2[2 * dst], w * hv.x, w * hv.y);
}

// ---------------- 5: normalize + bias + log_softmax ----------------
__global__ void __launch_bounds__(256)
final_kernel(const float* __restrict__ b2, float* __restrict__ out) {
    int n = blockIdx.x * 256 + threadIdx.x;
    if (n >= NN) return;
    float z = g_z2[n];
    float o0 = g_S2[2 * n]     / z + __ldg(&b2[0]);
    float o1 = g_S2[2 * n + 1] / z + __ldg(&b2[1]);
    float m = fmaxf(o0, o1);
    float lse = m + logf(__expf(o0 - m) + __expf(o1 - m));
    out[2 * n]     = o0 - lse;
    out[2 * n + 1] = o1 - lse;
}

// ---------------- launch ----------------
extern "C" void kernel_launch(void* const* d_in, const int* in_sizes, int n_in,
                              void* d_out, int out_size) {
    const float*     x     = (const float*)d_in[0];
    const long long* eidx  = (const long long*)d_in[1];
    const float*     W1    = (const float*)d_in[2];
    const float*     a1s   = (const float*)d_in[3];
    const float*     a1d   = (const float*)d_in[4];
    const float*     b1    = (const float*)d_in[5];
    const float*     W2    = (const float*)d_in[6];
    const float*     a2s   = (const float*)d_in[7];
    const float*     a2d   = (const float*)d_in[8];
    const float*     b2    = (const float*)d_in[9];
    float*           out   = (float*)d_out;

    cudaFuncSetAttribute(gemm1_kernel, cudaFuncAttributeMaxDynamicSharedMemorySize, GEMM1_SMEM);

    detect_kernel<<<1, 256>>>(eidx);
    gemm1_kernel<<<NN / 32, 256, GEMM1_SMEM>>>(x, W1, a1s, a1d);
    edge1_kernel<<<(NE * 8 + 255) / 256, 256>>>(eidx);
    epi1_kernel<<<NN / 8, 256>>>(b1, W2, a2s, a2d);
    edge2_kernel<<<(NE + 255) / 256, 256>>>(eidx);
    final_kernel<<<(NN + 255) / 256, 256>>>(b2, out);
}

// round 2
// speedup vs baseline: 1.4613x; 1.4613x over previous
#include <cuda_runtime.h>

#define NN   100000
#define NE   1600000
#define FIN  165
#define NEG  0.2f

// ---------------- scratch (static device globals; no runtime alloc) ----------------
__device__ __align__(16) float g_h1[(long)NN * 64];   // h1 = x@W1, [N,8,8]
__device__ float g_as1[NN * 8];
__device__ float g_ad1[NN * 8];
__device__ __align__(8)  float g_h2[NN * 2];
__device__ float g_as2[NN];
__device__ float g_ad2[NN];
__device__ int   g_is64;

// CSR scratch
__device__ int g_deg[NN];
__device__ int g_tmp[NN];
__device__ int g_row[NN + 1];
__device__ int g_cursor[NN];
__device__ int g_bsum[128];
__device__ int g_boff[128];
__device__ int g_srcidx[NE];

__device__ __forceinline__ float lrelu(float t) { return t > 0.f ? t : NEG * t; }

// ---------------- 0: edge_index dtype detection (int64 vs int32) ----------------
__global__ void detect_kernel(const long long* __restrict__ e) {
    long long v = e[threadIdx.x];
    int bad = (v < 0 || v >= NN);
    int any = __syncthreads_or(bad);
    if (threadIdx.x == 0) g_is64 = !any;
}

// ---------------- CSR build ----------------
__global__ void __launch_bounds__(256) zero_kernel() {
    int i = blockIdx.x * 256 + threadIdx.x;
    if (i < NN) g_deg[i] = 0;
}

__global__ void __launch_bounds__(256) hist_kernel(const long long* __restrict__ eidx) {
    int e = blockIdx.x * 256 + threadIdx.x;
    if (e >= NE) return;
    int dst = g_is64 ? (int)eidx[NE + e] : ((const int*)eidx)[NE + e];
    atomicAdd(&g_deg[dst], 1);
}

#define NB_SCAN 98   // ceil(100000/1024)
__global__ void __launch_bounds__(1024) scanA_kernel() {
    __shared__ int s[1024];
    int tid = threadIdx.x;
    int i = blockIdx.x * 1024 + tid;
    int d = (i < NN) ? g_deg[i] : 0;
    s[tid] = d;
    __syncthreads();
#pragma unroll
    for (int o = 1; o < 1024; o <<= 1) {
        int v = (tid >= o) ? s[tid - o] : 0;
        __syncthreads();
        s[tid] += v;
        __syncthreads();
    }
    if (i < NN) g_tmp[i] = s[tid];
    if (tid == 1023) g_bsum[blockIdx.x] = s[1023];
}

__global__ void __launch_bounds__(128) scanB_kernel() {
    __shared__ int s[128];
    int t = threadIdx.x;
    int d = (t < NB_SCAN) ? g_bsum[t] : 0;
    s[t] = d;
    __syncthreads();
#pragma unroll
    for (int o = 1; o < 128; o <<= 1) {
        int v = (t >= o) ? s[t - o] : 0;
        __syncthreads();
        s[t] += v;
        __syncthreads();
    }
    if (t < NB_SCAN) g_boff[t] = s[t] - d;   // exclusive
}

__global__ void __launch_bounds__(1024) scanC_kernel() {
    int i = blockIdx.x * 1024 + threadIdx.x;
    if (i >= NN) return;
    int incl = g_tmp[i] + g_boff[blockIdx.x];
    int r = incl - g_deg[i];
    g_row[i] = r;
    g_cursor[i] = r;
    if (i == NN - 1) g_row[NN] = incl;
}

__global__ void __launch_bounds__(256) scatter_kernel(const long long* __restrict__ eidx) {
    int e = blockIdx.x * 256 + threadIdx.x;
    if (e >= NE) return;
    int src, dst;
    if (g_is64) { src = (int)eidx[e]; dst = (int)eidx[NE + e]; }
    else { const int* e32 = (const int*)eidx; src = e32[e]; dst = e32[NE + e]; }
    int pos = atomicAdd(&g_cursor[dst], 1);
    g_srcidx[pos] = src;
}

// ---------------- gemm1: h1 = x@W1, alpha_src1, alpha_dst1 ----------------
// 128 nodes/block, 256 threads; thread (tn,tc) computes nodes {tn,tn+32,tn+64,tn+96}, cols tc*8..tc*8+7
#define G1_NODES 128
#define G1_SMEM ((FIN * 64 + G1_NODES * FIN) * 4)
__global__ void __launch_bounds__(256)
gemm1_kernel(const float* __restrict__ x, const float* __restrict__ W1,
             const float* __restrict__ a1s, const float* __restrict__ a1d) {
    extern __shared__ float sm[];
    float* Ws = sm;                  // [165][64]
    float* xs = sm + FIN * 64;       // [128][165]
    int tid = threadIdx.x;
    long base = (long)blockIdx.x * G1_NODES * FIN;
    long lim = (long)NN * FIN - base;
    for (int i = tid; i < FIN * 64; i += 256) Ws[i] = W1[i];
    for (int i = tid; i < G1_NODES * FIN; i += 256) xs[i] = (i < lim) ? x[base + i] : 0.f;
    __syncthreads();

    int tc = tid & 7, tn = tid >> 3;
    float acc[4][8] = {};
    const float* wp = Ws + tc * 8;
#pragma unroll 5
    for (int k = 0; k < FIN; ++k) {
        float4 w0 = *reinterpret_cast<const float4*>(wp + k * 64);
        float4 w1 = *reinterpret_cast<const float4*>(wp + k * 64 + 4);
#pragma unroll
        for (int i = 0; i < 4; ++i) {
            float xv = xs[(tn + 32 * i) * FIN + k];
            acc[i][0] += xv * w0.x; acc[i][1] += xv * w0.y;
            acc[i][2] += xv * w0.z; acc[i][3] += xv * w0.w;
            acc[i][4] += xv * w1.x; acc[i][5] += xv * w1.y;
            acc[i][6] += xv * w1.z; acc[i][7] += xv * w1.w;
        }
    }

#pragma unroll
    for (int i = 0; i < 4; ++i) {
        int n = blockIdx.x * G1_NODES + tn + 32 * i;
        if (n >= NN) continue;
        float as = 0.f, ad = 0.f;
#pragma unroll
        for (int j = 0; j < 8; ++j) {
            as += acc[i][j] * __ldg(&a1s[tc * 8 + j]);
            ad += acc[i][j] * __ldg(&a1d[tc * 8 + j]);
        }
        g_as1[n * 8 + tc] = as;
        g_ad1[n * 8 + tc] = ad;
        long o = (long)n * 64 + tc * 8;
        *reinterpret_cast<float4*>(&g_h1[o])     = make_float4(acc[i][0], acc[i][1], acc[i][2], acc[i][3]);
        *reinterpret_cast<float4*>(&g_h1[o + 4]) = make_float4(acc[i][4], acc[i][5], acc[i][6], acc[i][7]);
    }
}

// ---------------- gather1: layer-1 aggregation + epilogue + layer-2 prep ----------------
// warp per node; lane l -> cols (2l, 2l+1), head h = l>>2
__global__ void __launch_bounds__(256)
gather1_kernel(const float* __restrict__ b1, const float* __restrict__ W2,
               const float* __restrict__ a2s, const float* __restrict__ a2d) {
    int n = blockIdx.x * 8 + (threadIdx.x >> 5);
    int l = threadIdx.x & 31;
    int h = l >> 2;

    float ad_n = g_ad1[n * 8 + h];
    float2 acc;
    float z;
    {   // self-loop init
        float w = __expf(lrelu(g_as1[n * 8 + h] + ad_n));
        float2 hv = *reinterpret_cast<const float2*>(&g_h1[(long)n * 64 + 2 * l]);
        acc.x = w * hv.x; acc.y = w * hv.y; z = w;
    }

    int e0 = g_row[n], e1 = g_row[n + 1];
    for (int base = e0; base < e1; base += 32) {
        int cnt = min(32, e1 - base);
        int srcl = (l < cnt) ? __ldg(&g_srcidx[base + l]) : 0;
#pragma unroll 4
        for (int j = 0; j < cnt; ++j) {
            int s = __shfl_sync(0xffffffffu, srcl, j);
            float w = __expf(lrelu(__ldg(&g_as1[s * 8 + h]) + ad_n));
            float2 hv = *reinterpret_cast<const float2*>(&g_h1[(long)s * 64 + 2 * l]);
            z += w; acc.x += w * hv.x; acc.y += w * hv.y;
        }
    }

    // normalize + bias + elu
    float zi = 1.f / z;   // z identical across the 4 lanes of each head group
    float v0 = acc.x * zi + __ldg(&b1[2 * l]);
    float v1 = acc.y * zi + __ldg(&b1[2 * l + 1]);
    v0 = v0 > 0.f ? v0 : expm1f(v0);
    v1 = v1 > 0.f ? v1 : expm1f(v1);

    // h2 = out1 @ W2  (W2 is [64,2])
    float p0 = v0 * __ldg(&W2[4 * l])     + v1 * __ldg(&W2[4 * l + 2]);
    float p1 = v0 * __ldg(&W2[4 * l + 1]) + v1 * __ldg(&W2[4 * l + 3]);
#pragma unroll
    for (int o = 16; o; o >>= 1) {
        p0 += __shfl_xor_sync(0xffffffffu, p0, o);
        p1 += __shfl_xor_sync(0xffffffffu, p1, o);
    }
    if (l == 0) {
        float as = p0 * __ldg(&a2s[0]) + p1 * __ldg(&a2s[1]);
        float ad = p0 * __ldg(&a2d[0]) + p1 * __ldg(&a2d[1]);
        g_h2[2 * n] = p0; g_h2[2 * n + 1] = p1;
        g_as2[n] = as;    g_ad2[n] = ad;
    }
}

// ---------------- gather2: layer-2 aggregation + log_softmax ----------------
// warp per node; lanes stride edges
__global__ void __launch_bounds__(256)
gather2_kernel(const float* __restrict__ b2, float* __restrict__ out) {
    int n = blockIdx.x * 8 + (threadIdx.x >> 5);
    int l = threadIdx.x & 31;
    float ad_n = g_ad2[n];
    float z = 0.f, s0 = 0.f, s1 = 0.f;
    int e0 = g_row[n], e1 = g_row[n + 1];
    for (int e = e0 + l; e < e1; e += 32) {
        int s = __ldg(&g_srcidx[e]);
        float w = __expf(lrelu(__ldg(&g_as2[s]) + ad_n));
        float2 hv = *reinterpret_cast<const float2*>(&g_h2[2 * s]);
        z += w; s0 += w * hv.x; s1 += w * hv.y;
    }
    if (l == 0) {   // self-loop
        float w = __expf(lrelu(g_as2[n] + ad_n));
        z += w; s0 += w * g_h2[2 * n]; s1 += w * g_h2[2 * n + 1];
    }
#pragma unroll
    for (int o = 16; o; o >>= 1) {
        z  += __shfl_xor_sync(0xffffffffu, z, o);
        s0 += __shfl_xor_sync(0xffffffffu, s0, o);
        s1 += __shfl_xor_sync(0xffffffffu, s1, o);
    }
    if (l == 0) {
        float zi = 1.f / z;
        float o0 = s0 * zi + __ldg(&b2[0]);
        float o1 = s1 * zi + __ldg(&b2[1]);
        float m = fmaxf(o0, o1);
        float lse = m + logf(__expf(o0 - m) + __expf(o1 - m));
        out[2 * n]     = o0 - lse;
        out[2 * n + 1] = o1 - lse;
    }
}

// ---------------- launch ----------------
extern "C" void kernel_launch(void* const* d_in, const int* in_sizes, int n_in,
                              void* d_out, int out_size) {
    const float*     x    = (const float*)d_in[0];
    const long long* eidx = (const long long*)d_in[1];
    const float*     W1   = (const float*)d_in[2];
    const float*     a1s  = (const float*)d_in[3];
    const float*     a1d  = (const float*)d_in[4];
    const float*     b1   = (const float*)d_in[5];
    const float*     W2   = (const float*)d_in[6];
    const float*     a2s  = (const float*)d_in[7];
    const float*     a2d  = (const float*)d_in[8];
    const float*     b2   = (const float*)d_in[9];
    float*           out  = (float*)d_out;

    cudaFuncSetAttribute(gemm1_kernel, cudaFuncAttributeMaxDynamicSharedMemorySize, G1_SMEM);

    detect_kernel<<<1, 256>>>(eidx);
    zero_kernel<<<(NN + 255) / 256, 256>>>();
    hist_kernel<<<(NE + 255) / 256, 256>>>(eidx);
    scanA_kernel<<<NB_SCAN, 1024>>>();
    scanB_kernel<<<1, 128>>>();
    scanC_kernel<<<NB_SCAN, 1024>>>();
    scatter_kernel<<<(NE + 255) / 256, 256>>>(eidx);
    gemm1_kernel<<<(NN + G1_NODES - 1) / G1_NODES, 256, G1_SMEM>>>(x, W1, a1s, a1d);
    gather1_kernel<<<NN / 8, 256>>>(b1, W2, a2s, a2d);
    gather2_kernel<<<NN / 8, 256>>>(b2, out);
}